// round 1
// baseline (speedup 1.0000x reference)
#include <cuda_runtime.h>
#include <math.h>

// ---------------------------------------------------------------------------
// Problem constants
// ---------------------------------------------------------------------------
#define B_   4
#define S_   4096
#define T_   77
#define D_   1280
#define DT_  768
#define H_   8
#define HD_  160
#define RAD_ 64
#define M_BS (B_*S_)   // 16384
#define M_BT (B_*T_)   // 308
#define OFF_ ((size_t)M_BS * D_)   // 20971520 elements per output tensor

// ---------------------------------------------------------------------------
// Device scratch (static __device__ arrays -- no allocation at runtime)
// ---------------------------------------------------------------------------
__device__ float g_q  [M_BS * D_];
__device__ float g_Fg [M_BS * D_];
__device__ float g_F0 [M_BS * D_];
__device__ float g_F1 [M_BS * D_];
__device__ float g_k  [M_BT * D_];
__device__ float g_v  [M_BT * D_];
__device__ float g_Wk [D_ * DT_];
__device__ float g_Wv [D_ * DT_];
__device__ float g_Wo [D_ * D_];

// ---------------------------------------------------------------------------
// Fold LoRA (rank 4) into base weight:  W_eff[n,k] = W[n,k] + 0.25*sum_r B[n,r]*A[r,k]
// W: (N,K) row-major, A: (4,K), B: (N,4)
// ---------------------------------------------------------------------------
__global__ void fold_kernel(const float* __restrict__ W, const float* __restrict__ A,
                            const float* __restrict__ Bm, float* __restrict__ out,
                            int N, int K)
{
    int i = blockIdx.x * 256 + threadIdx.x;
    if (i >= N * K) return;
    int n = i / K;
    int k = i - n * K;
    float acc = W[i];
#pragma unroll
    for (int r = 0; r < 4; r++)
        acc += 0.25f * Bm[n * 4 + r] * A[r * K + k];
    out[i] = acc;
}

// ---------------------------------------------------------------------------
// Tiled SGEMM:  C[M,N] = A[M,K] @ B[N,K]^T  (+ bias[n])
// BM=BN=128, BK=8, 256 threads, 8x8 per thread. M may be ragged; N%128==0, K%8==0.
// ---------------------------------------------------------------------------
__global__ void __launch_bounds__(256) sgemm_kernel(
    const float* __restrict__ A, const float* __restrict__ Bm,
    const float* __restrict__ bias, float* __restrict__ C,
    int M, int N, int K)
{
    __shared__ float As[8][128];
    __shared__ float Bs[8][128];

    const int tid = threadIdx.x;
    const int bm  = blockIdx.y * 128;
    const int bn  = blockIdx.x * 128;
    const int tx  = tid & 15;        // 0..15  -> 8 cols each
    const int ty  = tid >> 4;        // 0..15  -> 8 rows each
    const int ldRow = tid >> 1;      // 0..127
    const int ldCol = (tid & 1) * 4; // 0 or 4

    float acc[8][8];
#pragma unroll
    for (int i = 0; i < 8; i++)
#pragma unroll
        for (int j = 0; j < 8; j++) acc[i][j] = 0.f;

    for (int k0 = 0; k0 < K; k0 += 8) {
        // load A tile (guard rows beyond M)
        float4 av = make_float4(0.f, 0.f, 0.f, 0.f);
        int gm = bm + ldRow;
        if (gm < M)
            av = *(const float4*)(A + (size_t)gm * K + k0 + ldCol);
        As[ldCol + 0][ldRow] = av.x;
        As[ldCol + 1][ldRow] = av.y;
        As[ldCol + 2][ldRow] = av.z;
        As[ldCol + 3][ldRow] = av.w;

        // load B tile (N is always a multiple of 128)
        float4 bv = *(const float4*)(Bm + (size_t)(bn + ldRow) * K + k0 + ldCol);
        Bs[ldCol + 0][ldRow] = bv.x;
        Bs[ldCol + 1][ldRow] = bv.y;
        Bs[ldCol + 2][ldRow] = bv.z;
        Bs[ldCol + 3][ldRow] = bv.w;

        __syncthreads();

#pragma unroll
        for (int k = 0; k < 8; k++) {
            float ra[8], rb[8];
#pragma unroll
            for (int i = 0; i < 8; i++) ra[i] = As[k][ty * 8 + i];
#pragma unroll
            for (int j = 0; j < 8; j++) rb[j] = Bs[k][tx * 8 + j];
#pragma unroll
            for (int i = 0; i < 8; i++)
#pragma unroll
                for (int j = 0; j < 8; j++)
                    acc[i][j] += ra[i] * rb[j];
        }
        __syncthreads();
    }

#pragma unroll
    for (int i = 0; i < 8; i++) {
        int m = bm + ty * 8 + i;
        if (m >= M) continue;
#pragma unroll
        for (int j = 0; j < 8; j++) {
            int n = bn + tx * 8 + j;
            float v = acc[i][j];
            if (bias) v += bias[n];
            C[(size_t)m * N + n] = v;
        }
    }
}

// ---------------------------------------------------------------------------
// Attention: one warp per query row, K/V (for one (b,h) head) staged in smem.
// Tkv <= 96 (scores live in 3 regs/lane). Optional gather indices (toks).
// maybe64: detect int64 index buffer (all odd 32-bit words of first 32B zero).
// Output layout: F[(b*S+s)*D + h*HD + d]  (heads concatenated -> matches ref)
// ---------------------------------------------------------------------------
__global__ void __launch_bounds__(256) attn_kernel(
    const float* __restrict__ q, const float* __restrict__ k,
    const float* __restrict__ v, const int* __restrict__ toks,
    int Tkv, int maybe64, float* __restrict__ outF)
{
    extern __shared__ float sm[];
    float* Ks = sm;
    float* Vs = sm + Tkv * HD_;

    const int b  = blockIdx.z;
    const int h  = blockIdx.y;
    const int s0 = blockIdx.x * 64;
    const int tid = threadIdx.x;

    int is64 = 0;
    if (toks && maybe64) {
        // int64 values in [0,77): high words are zero. int32 buffer having all
        // odd entries zero has probability ~(1/77)^4 -- negligible.
        is64 = (toks[1] == 0 && toks[3] == 0 && toks[5] == 0 && toks[7] == 0);
    }

    for (int i = tid; i < Tkv * HD_; i += 256) {
        int t = i / HD_;
        int d = i - t * HD_;
        int trow = t;
        if (toks) trow = is64 ? toks[2 * t] : toks[t];
        size_t gidx = ((size_t)b * T_ + trow) * D_ + h * HD_ + d;
        Ks[i] = k[gidx];
        Vs[i] = v[gidx];
    }
    __syncthreads();

    const int warp = tid >> 5;
    const int lane = tid & 31;
    const float scale = 0.07905694150420949f;  // 160^-0.5
    const unsigned FULL = 0xffffffffu;

    for (int itq = 0; itq < 8; itq++) {
        int s = s0 + warp * 8 + itq;
        size_t base = ((size_t)b * S_ + s) * D_ + h * HD_;

        float qr[5];
#pragma unroll
        for (int j = 0; j < 5; j++) qr[j] = q[base + lane + 32 * j];

        float sc0 = 0.f, sc1 = 0.f, sc2 = 0.f;
        for (int t = 0; t < Tkv; t++) {
            float p = 0.f;
            const float* kr = Ks + t * HD_;
#pragma unroll
            for (int j = 0; j < 5; j++) p += qr[j] * kr[lane + 32 * j];
#pragma unroll
            for (int off = 16; off; off >>= 1)
                p += __shfl_xor_sync(FULL, p, off);
            float val = p * scale;
            if ((t & 31) == lane) {
                int slot = t >> 5;
                if      (slot == 0) sc0 = val;
                else if (slot == 1) sc1 = val;
                else                sc2 = val;
            }
        }

        // softmax over Tkv entries distributed across lanes
        float m = -1e30f;
        if (lane      < Tkv) m = fmaxf(m, sc0);
        if (32 + lane < Tkv) m = fmaxf(m, sc1);
        if (64 + lane < Tkv) m = fmaxf(m, sc2);
#pragma unroll
        for (int off = 16; off; off >>= 1)
            m = fmaxf(m, __shfl_xor_sync(FULL, m, off));

        float ssum = 0.f;
        sc0 = (lane      < Tkv) ? expf(sc0 - m) : 0.f;
        sc1 = (32 + lane < Tkv) ? expf(sc1 - m) : 0.f;
        sc2 = (64 + lane < Tkv) ? expf(sc2 - m) : 0.f;
        ssum = sc0 + sc1 + sc2;
#pragma unroll
        for (int off = 16; off; off >>= 1)
            ssum += __shfl_xor_sync(FULL, ssum, off);
        float inv = 1.f / ssum;
        sc0 *= inv; sc1 *= inv; sc2 *= inv;

        float o[5] = {0.f, 0.f, 0.f, 0.f, 0.f};
        for (int t = 0; t < Tkv; t++) {
            float src = (t < 32) ? sc0 : ((t < 64) ? sc1 : sc2);
            float p = __shfl_sync(FULL, src, t & 31);
            const float* vr = Vs + t * HD_;
#pragma unroll
            for (int j = 0; j < 5; j++) o[j] += p * vr[lane + 32 * j];
        }
#pragma unroll
        for (int j = 0; j < 5; j++) outF[base + lane + 32 * j] = o[j];
    }
}

// ---------------------------------------------------------------------------
// Feature adapter:  out = x + up( gelu( down(x) ) ),  exact erf gelu.
// dW: (64,1280), uW: (1280,64). 8 rows per block to amortize weight traffic.
// ---------------------------------------------------------------------------
#define RPB 8
__global__ void __launch_bounds__(256) adapter_kernel(
    const float* __restrict__ x,
    const float* __restrict__ dW, const float* __restrict__ db,
    const float* __restrict__ uW, const float* __restrict__ ub,
    float* __restrict__ out)
{
    __shared__ float xs[RPB][D_];
    __shared__ float hb[RPB][RAD_];

    const size_t row0 = (size_t)blockIdx.x * RPB;
    const int tid = threadIdx.x;
    const unsigned FULL = 0xffffffffu;

    for (int i = tid; i < RPB * D_; i += 256) {
        int r = i / D_;
        int d = i - r * D_;
        xs[r][d] = x[(row0 + r) * D_ + d];
    }
    __syncthreads();

    const int warp = tid >> 5;
    const int lane = tid & 31;

    for (int j = warp; j < RAD_; j += 8) {
        const float* w = dW + (size_t)j * D_;
        float ps[RPB];
#pragma unroll
        for (int r = 0; r < RPB; r++) ps[r] = 0.f;
        for (int i = lane; i < D_; i += 32) {
            float wv = w[i];
#pragma unroll
            for (int r = 0; r < RPB; r++) ps[r] += xs[r][i] * wv;
        }
#pragma unroll
        for (int r = 0; r < RPB; r++) {
#pragma unroll
            for (int off = 16; off; off >>= 1)
                ps[r] += __shfl_xor_sync(FULL, ps[r], off);
        }
        if (lane == 0) {
            float dbj = db[j];
#pragma unroll
            for (int r = 0; r < RPB; r++) {
                float hv = ps[r] + dbj;
                hb[r][j] = 0.5f * hv * (1.f + erff(hv * 0.7071067811865475f));
            }
        }
    }
    __syncthreads();

    for (int d = tid; d < D_; d += 256) {
        float o[RPB];
        float ubd = ub[d];
#pragma unroll
        for (int r = 0; r < RPB; r++) o[r] = xs[r][d] + ubd;
        const float* uwp = uW + (size_t)d * RAD_;
#pragma unroll 16
        for (int j = 0; j < RAD_; j++) {
            float uv = uwp[j];
#pragma unroll
            for (int r = 0; r < RPB; r++) o[r] += hb[r][j] * uv;
        }
#pragma unroll
        for (int r = 0; r < RPB; r++) out[(row0 + r) * D_ + d] = o[r];
    }
}

// ---------------------------------------------------------------------------
// Launch
// ---------------------------------------------------------------------------
extern "C" void kernel_launch(void* const* d_in, const int* in_sizes, int n_in,
                              void* d_out, int out_size)
{
    const float* hs    = (const float*)d_in[0];
    const float* enc   = (const float*)d_in[1];
    const int*   e0    = (const int*)  d_in[2];
    const int*   e1    = (const int*)  d_in[3];
    const float* Wq    = (const float*)d_in[4];
    const float* Wk    = (const float*)d_in[5];
    const float* Wv    = (const float*)d_in[6];
    const float* Wo    = (const float*)d_in[7];
    const float* bo    = (const float*)d_in[8];
    const float* lkA   = (const float*)d_in[9];
    const float* lkB   = (const float*)d_in[10];
    const float* lvA   = (const float*)d_in[11];
    const float* lvB   = (const float*)d_in[12];
    const float* loA   = (const float*)d_in[13];
    const float* loB   = (const float*)d_in[14];
    const float* a0dW  = (const float*)d_in[15];
    const float* a0db  = (const float*)d_in[16];
    const float* a0uW  = (const float*)d_in[17];
    const float* a0ub  = (const float*)d_in[18];
    const float* a1dW  = (const float*)d_in[19];
    const float* a1db  = (const float*)d_in[20];
    const float* a1uW  = (const float*)d_in[21];
    const float* a1ub  = (const float*)d_in[22];

    float *qp, *fgp, *f0p, *f1p, *kp, *vp, *wkp, *wvp, *wop;
    cudaGetSymbolAddress((void**)&qp,  g_q);
    cudaGetSymbolAddress((void**)&fgp, g_Fg);
    cudaGetSymbolAddress((void**)&f0p, g_F0);
    cudaGetSymbolAddress((void**)&f1p, g_F1);
    cudaGetSymbolAddress((void**)&kp,  g_k);
    cudaGetSymbolAddress((void**)&vp,  g_v);
    cudaGetSymbolAddress((void**)&wkp, g_Wk);
    cudaGetSymbolAddress((void**)&wvp, g_Wv);
    cudaGetSymbolAddress((void**)&wop, g_Wo);

    float* out = (float*)d_out;

    // 1) fold LoRA into base weights
    fold_kernel<<<(D_ * DT_ + 255) / 256, 256>>>(Wk, lkA, lkB, wkp, D_, DT_);
    fold_kernel<<<(D_ * DT_ + 255) / 256, 256>>>(Wv, lvA, lvB, wvp, D_, DT_);
    fold_kernel<<<(D_ * D_  + 255) / 256, 256>>>(Wo, loA, loB, wop, D_, D_);

    // 2) k, v projections (M=308)
    dim3 gkv(D_ / 128, (M_BT + 127) / 128);
    sgemm_kernel<<<gkv, 256>>>(enc, wkp, nullptr, kp, M_BT, D_, DT_);
    sgemm_kernel<<<gkv, 256>>>(enc, wvp, nullptr, vp, M_BT, D_, DT_);

    // 3) q projection (M=16384)
    dim3 gq(D_ / 128, M_BS / 128);
    sgemm_kernel<<<gq, 256>>>(hs, Wq, nullptr, qp, M_BS, D_, D_);

    // 4) attention (global + two entity-masked)
    cudaFuncSetAttribute(attn_kernel,
                         cudaFuncAttributeMaxDynamicSharedMemorySize, 101376);
    dim3 ga(S_ / 64, H_, B_);
    attn_kernel<<<ga, 256, (size_t)T_ * HD_ * 2 * sizeof(float)>>>(
        qp, kp, vp, nullptr, T_, 0, fgp);
    attn_kernel<<<ga, 256, (size_t)8 * HD_ * 2 * sizeof(float)>>>(
        qp, kp, vp, e0, 8, 1, f0p);
    attn_kernel<<<ga, 256, (size_t)12 * HD_ * 2 * sizeof(float)>>>(
        qp, kp, vp, e1, 12, 0, f1p);

    // 5) adapters -> F_0, F_1 output slots
    adapter_kernel<<<M_BS / RPB, 256>>>(f0p, a0dW, a0db, a0uW, a0ub, out + OFF_);
    adapter_kernel<<<M_BS / RPB, 256>>>(f1p, a1dW, a1db, a1uW, a1ub, out + 2 * OFF_);

    // 6) output projection (with folded LoRA + bias) -> out slot
    sgemm_kernel<<<gq, 256>>>(fgp, wop, bo, out, M_BS, D_, D_);
}